// round 17
// baseline (speedup 1.0000x reference)
#include <cuda_runtime.h>
#include <cstdint>

#define B 64
#define S 128
#define L 1024
#define H 512
#define E 256
#define V 64

struct __align__(256) Scratch {
    float h0[2][B * H], c0[2][B * H];
    float h1[2][B * H], c1[2][B * H];
    float h2[2][B * H], c2[2][B * H];
    float r[B * H];
    float q[B * H];
    float hidden[B * H];
    float P[H * H], p0[H];
    float A2[4 * H * H], cbias[4 * H];
    float w1b[H * H], b1p[H];
    float EW[V * 4 * H];
    float am[B * 2], az[B * 2];
    float ar[B * 2 * H];
    int yflag;
};
__device__ Scratch g_s;
__device__ unsigned g_grp[8 * 32];
__device__ unsigned g_root;
__device__ unsigned g_rel[8 * 32];

__device__ __forceinline__ void fma2(unsigned long long& a,
                                     unsigned long long x,
                                     unsigned long long w) {
    asm("fma.rn.f32x2 %0, %1, %2, %3;" : "=l"(a) : "l"(x), "l"(w), "l"(a));
}
__device__ __forceinline__ float red2(unsigned long long a) {
    float lo, hi;
    asm("mov.b64 {%0,%1}, %2;" : "=f"(lo), "=f"(hi) : "l"(a));
    return lo + hi;
}

// Two-level grid barrier (R10-proven: full fences). nblk >= 8.
__device__ __forceinline__ void grid_sync(int nblk, unsigned& ph) {
    ph++;
    __syncthreads();
    if (threadIdx.x == 0) {
        int g = blockIdx.x & 7;
        unsigned ng = (unsigned)((nblk + 7 - g) >> 3);
        __threadfence();
        unsigned o = atomicAdd(&g_grp[g * 32], 1u);
        if (o + 1u == ng * ph) {
            __threadfence();
            unsigned ro = atomicAdd(&g_root, 1u);
            if (ro + 1u == 8u * ph) {
                __threadfence();
                #pragma unroll
                for (int i = 0; i < 8; i++)
                    *((volatile unsigned*)&g_rel[i * 32]) = ph;
            }
        }
        while (*((volatile unsigned*)&g_rel[g * 32]) < ph) { }
        __threadfence();
    }
    __syncthreads();
}

__device__ __forceinline__ void cp16(unsigned dst, const float* __restrict__ src) {
    asm volatile("cp.async.cg.shared.global [%0], [%1], 16;"
                 :: "r"(dst), "l"(src));
}
#define CP_COMMIT() asm volatile("cp.async.commit_group;")
template <int N>
__device__ __forceinline__ void cp_wait() {
    asm volatile("cp.async.wait_group %0;" :: "n"(N));
}
// one 16x512 fp32 tile (32KB)
__device__ __forceinline__ void copy_tile_async(float* dst,
                                                const float* __restrict__ src,
                                                int tid) {
    unsigned d = (unsigned)__cvta_generic_to_shared(dst);
    #pragma unroll
    for (int u = 0; u < 8; u++) {
        int fo = (tid + u * 256) * 4;
        cp16(d + fo * 4, src + fo);
    }
}

#define XS_SZ (64 * 132)
#define SM_XS 0
#define SM_WS3 (3 * XS_SZ)
#define WS_SZ (16 * 128)
#define SM_ABUF 0
#define ATILE (16 * 512)
#define SMEM_FLOATS (4 * ATILE + 32)

__global__ void init_kernel(const void* y) {
    int i = blockIdx.x * blockDim.x + threadIdx.x;
    if (i == 0) {
        g_root = 0u;
        const int* yi = (const int*)y;
        int f = 1;
        for (int k = 0; k < 128; k++)
            if (yi[2 * k + 1] != 0) { f = 0; break; }
        g_s.yflag = f;
    }
    if (i < 8 * 32) { g_grp[i] = 0u; g_rel[i] = 0u; }
    if (i < B * H) {
        g_s.h0[0][i] = 0.f; g_s.c0[0][i] = 0.f;
        g_s.h1[0][i] = 0.f; g_s.c1[0][i] = 0.f;
        g_s.h2[0][i] = 0.f; g_s.c2[0][i] = 0.f;
        g_s.r[i] = 0.f;
    }
}

// ---- preamble tile bodies (32x32, 256 thr) --------------------------------
__device__ void tileP_body(int j0, int k0, const float* __restrict__ Wh,
                           const float* __restrict__ Ws, float* sm) {
    float (*As)[33] = (float(*)[33])sm;
    float (*Bs)[33] = (float(*)[33])(sm + 32 * 33);
    int tid = threadIdx.x, tx = tid & 31, ty = tid >> 5;
    float acc[4] = {0.f, 0.f, 0.f, 0.f};
    for (int i0 = 0; i0 < H; i0 += 32) {
        #pragma unroll
        for (int u = 0; u < 4; u++) {
            int idx = tid + u * 256, ii = idx >> 5, cc = idx & 31;
            As[ii][cc] = Wh[(i0 + ii) * H + j0 + cc];
            Bs[ii][cc] = Ws[(i0 + ii) * H + k0 + cc];
        }
        __syncthreads();
        #pragma unroll
        for (int ii = 0; ii < 32; ii++) {
            float bv = Bs[ii][tx];
            #pragma unroll
            for (int rr = 0; rr < 4; rr++) acc[rr] += As[ii][ty + 8 * rr] * bv;
        }
        __syncthreads();
    }
    #pragma unroll
    for (int rr = 0; rr < 4; rr++)
        g_s.P[(j0 + ty + 8 * rr) * H + k0 + tx] = acc[rr];
    __syncthreads();
}

__device__ void tileAB_body(const float* __restrict__ A, int lda, int offA,
                            const float* __restrict__ Bm, int ldb,
                            float* __restrict__ Cm, int ldc,
                            int n0, int m0, float* sm) {
    float (*As)[33] = (float(*)[33])sm;
    float (*Bs)[33] = (float(*)[33])(sm + 32 * 33);
    int tid = threadIdx.x, tx = tid & 31, ty = tid >> 5;
    float acc[4] = {0.f, 0.f, 0.f, 0.f};
    for (int k0 = 0; k0 < H; k0 += 32) {
        #pragma unroll
        for (int u = 0; u < 4; u++) {
            int idx = tid + u * 256, rr = idx >> 5, cc = idx & 31;
            As[rr][cc] = A[(m0 + rr) * lda + offA + k0 + cc];
            Bs[rr][cc] = Bm[(k0 + rr) * ldb + n0 + cc];
        }
        __syncthreads();
        #pragma unroll
        for (int kk = 0; kk < 32; kk++) {
            float bv = Bs[kk][tx];
            #pragma unroll
            for (int rr = 0; rr < 4; rr++) acc[rr] += As[ty + 8 * rr][kk] * bv;
        }
        __syncthreads();
    }
    #pragma unroll
    for (int rr = 0; rr < 4; rr++)
        Cm[(m0 + ty + 8 * rr) * ldc + n0 + tx] = acc[rr];
    __syncthreads();
}

__device__ void tileEW_body(const float* __restrict__ emb,
                            const float* __restrict__ Wih,
                            const float* __restrict__ bih,
                            const float* __restrict__ bhh,
                            int v0, int j0, float* sm) {
    float (*As)[33] = (float(*)[33])sm;
    float (*Bs)[33] = (float(*)[33])(sm + 32 * 33);
    int tid = threadIdx.x, tx = tid & 31, ty = tid >> 5;
    float acc[4] = {0.f, 0.f, 0.f, 0.f};
    for (int k0 = 0; k0 < E; k0 += 32) {
        #pragma unroll
        for (int u = 0; u < 4; u++) {
            int idx = tid + u * 256, rr = idx >> 5, cc = idx & 31;
            As[rr][cc] = emb[(v0 + rr) * E + k0 + cc];
            Bs[rr][cc] = Wih[(j0 + rr) * (E + H) + k0 + cc];
        }
        __syncthreads();
        #pragma unroll
        for (int kk = 0; kk < 32; kk++) {
            #pragma unroll
            for (int rr = 0; rr < 4; rr++)
                acc[rr] += As[ty + 8 * rr][kk] * Bs[tx][kk];
        }
        __syncthreads();
    }
    #pragma unroll
    for (int rr = 0; rr < 4; rr++) {
        int v = v0 + ty + 8 * rr, j = j0 + tx;
        g_s.EW[v * (4 * H) + j] = acc[rr] + bih[j] + bhh[j];
    }
    __syncthreads();
}

__device__ void vec_p0(int part, const float* __restrict__ Wh,
                       const float* __restrict__ Wsb) {
    int j = part * 256 + threadIdx.x;
    float a = 0.f;
    for (int i = 0; i < H; i++) a += Wh[i * H + j] * Wsb[i];
    g_s.p0[j] = a;
}
__device__ void vec_cbias(int part, const float* __restrict__ Wih,
                          const float* __restrict__ Whb) {
    int j = part * 256 + threadIdx.x;
    float a = 0.f;
    for (int k = 0; k < H; k++) a += Wih[j * (E + H) + E + k] * Whb[k];
    g_s.cbias[j] = a;
}
__device__ void vec_b1p(int part, const float* __restrict__ W1,
                        const float* __restrict__ b1,
                        const float* __restrict__ Whb) {
    int n = part * 256 + threadIdx.x;
    float a = b1[n];
    for (int k = 0; k < H; k++) a += W1[n * 2 * H + H + k] * Whb[k];
    g_s.b1p[n] = a;
}

// ---- cp.async chunk staging ----------------------------------------------
__device__ __forceinline__ void x_issue(float* xsb, int tid, int k0,
                                        const float* __restrict__ xlo,
                                        const float* __restrict__ xhi) {
    const float* xb = (k0 < H) ? xlo + k0 : xhi + (k0 - H);
    unsigned xd = (unsigned)__cvta_generic_to_shared(xsb);
    #pragma unroll
    for (int u = 0; u < 8; u++) {
        int s = tid + u * 256;
        int bb = s >> 5, kk4 = (s & 31) * 4;
        cp16(xd + (bb * 132 + kk4) * 4, xb + bb * H + kk4);
    }
}
__device__ __forceinline__ void w16_issue(float* wsb, int tid, int k0, int jbase,
                                          const float* __restrict__ Wlo,
                                          const float* __restrict__ Whi) {
    const float* wb = (k0 < H) ? Wlo + k0 : Whi + (k0 - H);
    unsigned wd = (unsigned)__cvta_generic_to_shared(wsb);
    #pragma unroll
    for (int u = 0; u < 2; u++) {
        int s = tid + u * 256;
        int r16 = s >> 5, kk4 = (s & 31) * 4;
        int row = (r16 >> 2) * H + jbase + (r16 & 3);
        cp16(wd + (r16 * 128 + kk4) * 4, wb + row * H + kk4);
    }
}
__device__ __forceinline__ void w4_issue(float* wsb, int tid, int k0, int nbase,
                                         int K1,
                                         const float* __restrict__ Wa, int ldwa,
                                         const float* __restrict__ Wb, int ldwb) {
    if (tid < 128) {
        const float* wb; int ld;
        if (k0 < K1) { wb = Wa + (size_t)nbase * ldwa + k0; ld = ldwa; }
        else         { wb = Wb + (size_t)nbase * ldwb + (k0 - K1); ld = ldwb; }
        int rr = tid >> 5, kk4 = (tid & 31) * 4;
        unsigned wd = (unsigned)__cvta_generic_to_shared(wsb);
        cp16(wd + (rr * 128 + kk4) * 4, wb + rr * ld + kk4);
    }
}

// ---- LSTM body, K=1024, triple-buffered depth-2 prefetch ------------------
__device__ void lstm_body(int jbase, int first, int t,
                          const void* __restrict__ yptr,
                          const float* __restrict__ xlo,
                          const float* __restrict__ hprev,
                          const float* __restrict__ cprev,
                          const float* __restrict__ Wlo,
                          const float* __restrict__ Whh,
                          const float* __restrict__ bih,
                          const float* __restrict__ bhh,
                          float* __restrict__ hout,
                          float* __restrict__ cout, float* sm) {
    int tid = threadIdx.x, b = tid & 63, jq = tid >> 6;

    x_issue(sm + SM_XS, tid, 0, xlo, hprev);
    w16_issue(sm + SM_WS3, tid, 0, jbase, Wlo, Whh);
    CP_COMMIT();
    x_issue(sm + SM_XS + XS_SZ, tid, 128, xlo, hprev);
    w16_issue(sm + SM_WS3 + WS_SZ, tid, 128, jbase, Wlo, Whh);
    CP_COMMIT();

    unsigned long long a0 = 0ull, a1 = 0ull, a2 = 0ull, a3 = 0ull;
    #pragma unroll 1
    for (int ch = 0; ch < 8; ch++) {
        if (ch + 2 < 8) {
            int nb = (ch + 2) % 3;
            x_issue(sm + SM_XS + nb * XS_SZ, tid, (ch + 2) * 128, xlo, hprev);
            w16_issue(sm + SM_WS3 + nb * WS_SZ, tid, (ch + 2) * 128, jbase,
                      Wlo, Whh);
            CP_COMMIT();
            cp_wait<2>();
        } else if (ch + 1 < 8) {
            cp_wait<1>();
        } else {
            cp_wait<0>();
        }
        __syncthreads();
        const float* xs = sm + SM_XS + (ch % 3) * XS_SZ + b * 132;
        const float* ws = sm + SM_WS3 + (ch % 3) * WS_SZ;
        #pragma unroll
        for (int kk = 0; kk < 128; kk += 4) {
            ulonglong2 xv = *(const ulonglong2*)(xs + kk);
            ulonglong2 w0 = *(const ulonglong2*)(ws + jq * 128 + kk);
            ulonglong2 w1 = *(const ulonglong2*)(ws + (4 + jq) * 128 + kk);
            ulonglong2 w2 = *(const ulonglong2*)(ws + (8 + jq) * 128 + kk);
            ulonglong2 w3 = *(const ulonglong2*)(ws + (12 + jq) * 128 + kk);
            fma2(a0, xv.x, w0.x); fma2(a0, xv.y, w0.y);
            fma2(a1, xv.x, w1.x); fma2(a1, xv.y, w1.y);
            fma2(a2, xv.x, w2.x); fma2(a2, xv.y, w2.y);
            fma2(a3, xv.x, w3.x); fma2(a3, xv.y, w3.y);
        }
        __syncthreads();
    }

    int j = jbase + jq;
    float gi = red2(a0), gf = red2(a1), gg = red2(a2), go = red2(a3);
    if (first) {
        int yy = g_s.yflag ? (int)((const long long*)yptr)[b * S + t]
                           : ((const int*)yptr)[b * S + t];
        const float* ew = g_s.EW + yy * (4 * H);
        gi += ew[j];         gf += ew[j + H];
        gg += ew[j + 2 * H]; go += ew[j + 3 * H];
        if (t > 0) {
            gi += g_s.cbias[j];         gf += g_s.cbias[j + H];
            gg += g_s.cbias[j + 2 * H]; go += g_s.cbias[j + 3 * H];
        }
    } else {
        gi += bih[j] + bhh[j];
        gf += bih[j + H] + bhh[j + H];
        gg += bih[j + 2 * H] + bhh[j + 2 * H];
        go += bih[j + 3 * H] + bhh[j + 3 * H];
    }
    float si = 1.f / (1.f + expf(-gi));
    float sf = 1.f / (1.f + expf(-gf));
    float so = 1.f / (1.f + expf(-go));
    float cv = sf * cprev[b * H + j] + si * tanhf(gg);
    cout[b * H + j] = cv;
    hout[b * H + j] = so * tanhf(cv);
}

// ---- Linear body, triple-buffered depth-2 prefetch ------------------------
template <bool RELU>
__device__ void linear_body(int nbase, const float* __restrict__ x1, int K1,
                            const float* __restrict__ x2,
                            const float* __restrict__ Wa, int ldwa,
                            const float* __restrict__ Wb, int ldwb, int Ktot,
                            const float* __restrict__ bias,
                            float* __restrict__ outp, int ldo, int off,
                            float* sm) {
    int tid = threadIdx.x, b = tid & 63, nq = tid >> 6;
    int NCH = Ktot >> 7;

    x_issue(sm + SM_XS, tid, 0, x1, x2);
    w4_issue(sm + SM_WS3, tid, 0, nbase, K1, Wa, ldwa, Wb, ldwb);
    CP_COMMIT();
    x_issue(sm + SM_XS + XS_SZ, tid, 128, x1, x2);
    w4_issue(sm + SM_WS3 + WS_SZ, tid, 128, nbase, K1, Wa, ldwa, Wb, ldwb);
    CP_COMMIT();

    unsigned long long acc = 0ull;
    #pragma unroll 1
    for (int ch = 0; ch < NCH; ch++) {
        if (ch + 2 < NCH) {
            int nb = (ch + 2) % 3;
            x_issue(sm + SM_XS + nb * XS_SZ, tid, (ch + 2) * 128, x1, x2);
            w4_issue(sm + SM_WS3 + nb * WS_SZ, tid, (ch + 2) * 128, nbase, K1,
                     Wa, ldwa, Wb, ldwb);
            CP_COMMIT();
            cp_wait<2>();
        } else if (ch + 1 < NCH) {
            cp_wait<1>();
        } else {
            cp_wait<0>();
        }
        __syncthreads();
        const float* xs = sm + SM_XS + (ch % 3) * XS_SZ + b * 132;
        const float* ws = sm + SM_WS3 + (ch % 3) * WS_SZ + nq * 128;
        #pragma unroll
        for (int kk = 0; kk < 128; kk += 4) {
            ulonglong2 xv = *(const ulonglong2*)(xs + kk);
            ulonglong2 wv = *(const ulonglong2*)(ws + kk);
            fma2(acc, xv.x, wv.x); fma2(acc, xv.y, wv.y);
        }
        __syncthreads();
    }
    int n = nbase + nq;
    float a = red2(acc) + bias[n];
    if (RELU) a = fmaxf(a, 0.f);
    outp[b * ldo + off + n] = a;
}

// ---- Per-warp online-softmax flash attention ------------------------------
// task=(b,half): 512 rows in 32 tiles of 16, quad-buffered, depth-2 prefetch,
// ONE sync per tile (buffer reuse distance 4 spans the next tile's sync).
// Each warp owns 2 rows/tile; per-warp (m,Z,racc) in registers; float4 lanes.
__device__ void attn_body(int task, const float* __restrict__ enc, float* sm) {
    int b = task >> 1, half = task & 1;
    float* buf = sm + SM_ABUF;
    int tid = threadIdx.x, w = tid >> 5, lane = tid & 31;
    const float* base = enc + ((size_t)b * L + (size_t)half * 512) * H;

    float4 q4[4];
    #pragma unroll
    for (int g = 0; g < 4; g++)
        q4[g] = ((const float4*)(g_s.q + b * H))[lane + g * 32];

    copy_tile_async(buf, base, tid);
    CP_COMMIT();
    copy_tile_async(buf + ATILE, base + 16 * 512, tid);
    CP_COMMIT();

    float m = -1e30f, Z = 0.f;
    float4 racc[4];
    #pragma unroll
    for (int g = 0; g < 4; g++) racc[g] = make_float4(0.f, 0.f, 0.f, 0.f);

    #pragma unroll 1
    for (int st = 0; st < 32; st++) {
        if (st + 2 < 32) {
            copy_tile_async(buf + ((st + 2) & 3) * ATILE,
                            base + (st + 2) * 16 * 512, tid);
            CP_COMMIT();
            cp_wait<2>();
        } else if (st + 1 < 32) {
            cp_wait<1>();
        } else {
            cp_wait<0>();
        }
        __syncthreads();                    // copies visible; also guards the
                                            // reuse of buf[(st+2)&3] issued above
        const float* cur = buf + (st & 3) * ATILE;
        float e[2];
        #pragma unroll
        for (int rr = 0; rr < 2; rr++) {
            const float4* row4 = (const float4*)(cur + (w * 2 + rr) * 512);
            float s = 0.f;
            #pragma unroll
            for (int g = 0; g < 4; g++) {
                float4 v = row4[lane + g * 32];
                s += q4[g].x * v.x + q4[g].y * v.y
                   + q4[g].z * v.z + q4[g].w * v.w;
            }
            #pragma unroll
            for (int o = 16; o > 0; o >>= 1)
                s += __shfl_xor_sync(0xffffffffu, s, o);
            e[rr] = s;
        }
        float tmax = fmaxf(e[0], e[1]);
        float mn = fmaxf(m, tmax);
        float scale = expf(m - mn);
        m = mn;
        float p0 = expf(e[0] - mn), p1 = expf(e[1] - mn);
        Z = Z * scale + p0 + p1;
        const float4* r04 = (const float4*)(cur + (w * 2) * 512);
        #pragma unroll
        for (int g = 0; g < 4; g++) {
            int c = lane + g * 32;
            float4 v0 = r04[c], v1 = r04[128 + c];
            racc[g].x = racc[g].x * scale + p0 * v0.x + p1 * v1.x;
            racc[g].y = racc[g].y * scale + p0 * v0.y + p1 * v1.y;
            racc[g].z = racc[g].z * scale + p0 * v0.z + p1 * v1.z;
            racc[g].w = racc[g].w * scale + p0 * v0.w + p1 * v1.w;
        }
    }
    // merge 8 warps through buffer 0 (disjoint from buffers 1-3 still in use
    // by laggards of the last tiles; all threads are past tile 28 = buf0)
    float* mw = buf;            // 8
    float* zw = buf + 8;        // 8
    float* rs = buf + 64;       // 8 x 512
    if (lane == 0) { mw[w] = m; zw[w] = Z; }
    __syncthreads();
    float M = mw[0];
    #pragma unroll
    for (int i = 1; i < 8; i++) M = fmaxf(M, mw[i]);
    float sc = expf(m - M);
    #pragma unroll
    for (int g = 0; g < 4; g++) {
        float4 v = make_float4(racc[g].x * sc, racc[g].y * sc,
                               racc[g].z * sc, racc[g].w * sc);
        ((float4*)(rs + w * 512))[lane + g * 32] = v;
    }
    __syncthreads();
    float r0 = 0.f, r1 = 0.f;
    #pragma unroll
    for (int w2 = 0; w2 < 8; w2++) {
        r0 += rs[w2 * 512 + tid];
        r1 += rs[w2 * 512 + tid + 256];
    }
    g_s.ar[(b * 2 + half) * H + tid] = r0;
    g_s.ar[(b * 2 + half) * H + tid + 256] = r1;
    if (tid == 0) {
        float Zt = 0.f;
        #pragma unroll
        for (int i = 0; i < 8; i++) Zt += zw[i] * expf(mw[i] - M);
        g_s.am[b * 2 + half] = M;
        g_s.az[b * 2 + half] = Zt;
    }
    __syncthreads();
}

__device__ void rwrite_body(int task) {
    int bb = task >> 1, j = ((task & 1) << 8) + threadIdx.x;
    float m0 = g_s.am[bb * 2], m1 = g_s.am[bb * 2 + 1];
    float mm = fmaxf(m0, m1);
    float z = expf(m0 - mm) * g_s.az[bb * 2]
            + expf(m1 - mm) * g_s.az[bb * 2 + 1];
    float w0 = expf(m0 - mm) / z, w1 = expf(m1 - mm) / z;
    g_s.r[bb * H + j] = w0 * g_s.ar[(bb * 2) * H + j]
                      + w1 * g_s.ar[(bb * 2 + 1) * H + j];
}

// ---------------------------------------------------------------------------
// Persistent decoder. Per step: S1'(att LSTM + prev MLP), S2'(rnn0 + prev
// logits), S3, S4(q), S5(attn), S6(rwrite) -> 6 barriers/step + tail.
// ---------------------------------------------------------------------------
__global__ void __launch_bounds__(256, 1)
decoder_kernel(int nblk,
               const void* __restrict__ yptr,
               const float* __restrict__ enc,
               const float* __restrict__ emb,
               const float* __restrict__ aWih, const float* __restrict__ aWhh,
               const float* __restrict__ abih, const float* __restrict__ abhh,
               const float* __restrict__ rWih, const float* __restrict__ rWhh,
               const float* __restrict__ rbih, const float* __restrict__ rbhh,
               const float* __restrict__ Wsw, const float* __restrict__ Wsb,
               const float* __restrict__ Whw, const float* __restrict__ Whb,
               const float* __restrict__ W1, const float* __restrict__ b1,
               const float* __restrict__ W2, const float* __restrict__ b2,
               float* __restrict__ out) {
    extern __shared__ __align__(16) float sm[];
    const int bid = blockIdx.x;
    unsigned ph = 0;

    // Preamble: P(256) A2(1024) w1b(256) EW(128) p0(2) cbias(8) b1p(2)
    for (int task = bid; task < 1676; task += nblk) {
        if (task < 256)
            tileP_body((task >> 4) * 32, (task & 15) * 32, Whw, Wsw, sm);
        else if (task < 1280) {
            int u = task - 256;
            tileAB_body(aWih, E + H, E, Whw, H, g_s.A2, H,
                        (u & 15) * 32, (u >> 4) * 32, sm);
        } else if (task < 1536) {
            int u = task - 1280;
            tileAB_body(W1, 2 * H, H, Whw, H, g_s.w1b, H,
                        (u & 15) * 32, (u >> 4) * 32, sm);
        } else if (task < 1664) {
            int u = task - 1536;
            tileEW_body(emb, aWih, abih, abhh, (u & 1) * 32, (u >> 1) * 32, sm);
        } else if (task < 1666) vec_p0(task - 1664, Whw, Wsb);
        else if (task < 1674) vec_cbias(task - 1666, aWih, Whb);
        else vec_b1p(task - 1674, W1, b1, Whb);
    }
    grid_sync(nblk, ph);

    for (int t = 0; t < S; t++) {
        int rp = t & 1, wp = rp ^ 1;
        const float* h2prev = g_s.h2[rp];   // == h2[wp(t-1)] for t > 0

        // S1': att LSTM (128) + MLP of step t-1 (128, t>0)
        {
            int ntask = t > 0 ? 256 : 128;
            for (int task = bid; task < ntask; task += nblk) {
                if (task < 128)
                    lstm_body(task * 4, 1, t, yptr, g_s.r, g_s.h0[rp],
                              g_s.c0[rp], g_s.A2, aWhh, nullptr, nullptr,
                              g_s.h0[wp], g_s.c0[wp], sm);
                else
                    linear_body<true>((task - 128) * 4, h2prev, H, g_s.r,
                                      W1, 2 * H, g_s.w1b, H, 2 * H,
                                      g_s.b1p, g_s.hidden, H, 0, sm);
            }
        }
        grid_sync(nblk, ph);

        // S2': rnn layer 0 (128) + logits of step t-1 (16, t>0)
        {
            int ntask = t > 0 ? 144 : 128;
            for (int task = bid; task < ntask; task += nblk) {
                if (task < 128)
                    lstm_body(task * 4, 0, t, nullptr, g_s.h0[wp], g_s.h1[rp],
                              g_s.c1[rp], rWih, rWhh, rbih, rbhh,
                              g_s.h1[wp], g_s.c1[wp], sm);
                else
                    linear_body<false>((task - 128) * 4, g_s.hidden, H, nullptr,
                                       W2, H, nullptr, 0, H,
                                       b2, out, S * V, (t - 1) * V, sm);
            }
        }
        grid_sync(nblk, ph);

        // S3: rnn layer 1
        for (int task = bid; task < 128; task += nblk)
            lstm_body(task * 4, 0, t, nullptr, g_s.h1[wp], g_s.h2[rp],
                      g_s.c2[rp], rWih + 4 * H * H, rWhh + 4 * H * H,
                      rbih + 4 * H, rbhh + 4 * H,
                      g_s.h2[wp], g_s.c2[wp], sm);
        grid_sync(nblk, ph);

        // S4: q = P @ h2 + p0
        for (int task = bid; task < 128; task += nblk)
            linear_body<false>(task * 4, g_s.h2[wp], H, nullptr,
                               g_s.P, H, nullptr, 0, H,
                               g_s.p0, g_s.q, H, 0, sm);
        grid_sync(nblk, ph);

        // S5: streamed flash attention
        for (int task = bid; task < 128; task += nblk)
            attn_body(task, enc, sm);
        grid_sync(nblk, ph);

        // S6: distributed softmax merge -> r
        for (int task = bid; task < 128; task += nblk)
            rwrite_body(task);
        grid_sync(nblk, ph);
    }

    // Tail: MLP + logits for t = 127 (h2[wp(127)] = h2[0])
    for (int task = bid; task < 128; task += nblk)
        linear_body<true>(task * 4, g_s.h2[0], H, g_s.r,
                          W1, 2 * H, g_s.w1b, H, 2 * H,
                          g_s.b1p, g_s.hidden, H, 0, sm);
    grid_sync(nblk, ph);
    for (int task = bid; task < 16; task += nblk)
        linear_body<false>(task * 4, g_s.hidden, H, nullptr,
                           W2, H, nullptr, 0, H,
                           b2, out, S * V, (S - 1) * V, sm);
}

// ---------------------------------------------------------------------------
extern "C" void kernel_launch(void* const* d_in, const int* in_sizes, int n_in,
                              void* d_out, int out_size) {
    const void*  y    = d_in[0];
    const float* enc  = (const float*)d_in[1];
    const float* emb  = (const float*)d_in[2];
    const float* aWih = (const float*)d_in[3];
    const float* aWhh = (const float*)d_in[4];
    const float* abih = (const float*)d_in[5];
    const float* abhh = (const float*)d_in[6];
    const float* rWih = (const float*)d_in[7];
    const float* rWhh = (const float*)d_in[8];
    const float* rbih = (const float*)d_in[9];
    const float* rbhh = (const float*)d_in[10];
    const float* Wsw  = (const float*)d_in[11];
    const float* Wsb  = (const float*)d_in[12];
    const float* Whw  = (const float*)d_in[13];
    const float* Whb  = (const float*)d_in[14];
    const float* W1   = (const float*)d_in[15];
    const float* b1   = (const float*)d_in[16];
    const float* W2   = (const float*)d_in[17];
    const float* b2   = (const float*)d_in[18];
    float* out = (float*)d_out;

    const int SMEM_BYTES = SMEM_FLOATS * (int)sizeof(float);  // ~128 KB
    static int configured = -1;
    if (configured < 0) {
        cudaFuncSetAttribute(decoder_kernel,
                             cudaFuncAttributeMaxDynamicSharedMemorySize,
                             SMEM_BYTES);
        configured = 1;
    }

    int dev = 0;
    cudaGetDevice(&dev);
    int sms = 128;
    cudaDeviceGetAttribute(&sms, cudaDevAttrMultiProcessorCount, dev);
    int nblk = sms < 128 ? sms : 128;

    init_kernel<<<(B * H + 255) / 256, 256>>>(y);
    decoder_kernel<<<nblk, 256, SMEM_BYTES>>>(
        nblk, y, enc, emb,
        aWih, aWhh, abih, abhh,
        rWih, rWhh, rbih, rbhh,
        Wsw, Wsb, Whw, Whb, W1, b1, W2, b2, out);
}